// round 5
// baseline (speedup 1.0000x reference)
#include <cuda_runtime.h>

// JPEG compress/decompress (DiffJPEG, factor=1.0) for [16,3,512,512] fp32 in [-1,1].
// One CTA = one 64x64 tile, 256 threads.
// Phase 1: gmem load (8 px/thread) -> YCbCr -> row DCT -> smem
// Phase 2: column DCT + diff-round quantize + column IDCT (float2, 2 cols/thread)
// Phase 3: smem -> row IDCT -> YCbCr->RGB -> gmem
// DC trick: subtract 128*64 from the DC coefficient instead of shifting pixels.

namespace {

constexpr int Hh = 512;
constexpr int Ww = 512;

// DCT-II basis: Dm[u][x] = cos((2x+1) u pi / 16)
__device__ static constexpr float Dm[8][8] = {
  { 1.f,          1.f,          1.f,          1.f,          1.f,          1.f,          1.f,          1.f         },
  { 0.98078528f,  0.83146961f,  0.55557023f,  0.19509032f, -0.19509032f, -0.55557023f, -0.83146961f, -0.98078528f },
  { 0.92387953f,  0.38268343f, -0.38268343f, -0.92387953f, -0.92387953f, -0.38268343f,  0.38268343f,  0.92387953f },
  { 0.83146961f, -0.19509032f, -0.98078528f, -0.55557023f,  0.55557023f,  0.98078528f,  0.19509032f, -0.83146961f },
  { 0.70710678f, -0.70710678f, -0.70710678f,  0.70710678f,  0.70710678f, -0.70710678f, -0.70710678f,  0.70710678f },
  { 0.55557023f, -0.98078528f,  0.19509032f,  0.83146961f, -0.83146961f, -0.19509032f,  0.98078528f, -0.55557023f },
  { 0.38268343f, -0.92387953f,  0.92387953f, -0.38268343f, -0.38268343f,  0.92387953f, -0.92387953f,  0.38268343f },
  { 0.19509032f, -0.55557023f,  0.83146961f, -0.98078528f,  0.98078528f, -0.83146961f,  0.55557023f, -0.19509032f },
};

__device__ static const float QY[64] = {
  16, 11, 10, 16, 24, 40, 51, 61,
  12, 12, 14, 19, 26, 58, 60, 55,
  14, 13, 16, 24, 40, 57, 69, 56,
  14, 17, 22, 29, 51, 87, 80, 62,
  18, 22, 37, 56, 68, 109, 103, 77,
  24, 35, 55, 64, 81, 104, 113, 92,
  49, 64, 78, 87, 103, 121, 120, 101,
  72, 92, 95, 98, 112, 100, 103, 99
};
__device__ static const float QC[64] = {
  17, 18, 24, 47, 99, 99, 99, 99,
  18, 21, 26, 66, 99, 99, 99, 99,
  24, 26, 56, 99, 99, 99, 99, 99,
  47, 66, 99, 99, 99, 99, 99, 99,
  99, 99, 99, 99, 99, 99, 99, 99,
  99, 99, 99, 99, 99, 99, 99, 99,
  99, 99, 99, 99, 99, 99, 99, 99,
  99, 99, 99, 99, 99, 99, 99, 99
};

// smem column swizzle: XOR bit2 with bit5. Keeps float4 groups intact,
// makes both linear and 8-strided block accesses conflict-free.
__device__ __forceinline__ int swzc(int c) { return c ^ ((c & 32) >> 3); }

// 1D 8-point DCT (even/odd split): out[k] = sum_j in[j] * Dm[k][j]
__device__ __forceinline__ void dct1(float* v) {
  float e0 = v[0] + v[7], e1 = v[1] + v[6], e2 = v[2] + v[5], e3 = v[3] + v[4];
  float o0 = v[0] - v[7], o1 = v[1] - v[6], o2 = v[2] - v[5], o3 = v[3] - v[4];
  v[0] = (e0 + e3) + (e1 + e2);
  v[4] = Dm[4][0] * ((e0 + e3) - (e1 + e2));
  v[2] = Dm[2][0]*e0 + Dm[2][1]*e1 + Dm[2][2]*e2 + Dm[2][3]*e3;
  v[6] = Dm[6][0]*e0 + Dm[6][1]*e1 + Dm[6][2]*e2 + Dm[6][3]*e3;
  v[1] = Dm[1][0]*o0 + Dm[1][1]*o1 + Dm[1][2]*o2 + Dm[1][3]*o3;
  v[3] = Dm[3][0]*o0 + Dm[3][1]*o1 + Dm[3][2]*o2 + Dm[3][3]*o3;
  v[5] = Dm[5][0]*o0 + Dm[5][1]*o1 + Dm[5][2]*o2 + Dm[5][3]*o3;
  v[7] = Dm[7][0]*o0 + Dm[7][1]*o1 + Dm[7][2]*o2 + Dm[7][3]*o3;
}

// 1D 8-point IDCT: out[k] = sum_j in[j] * Dm[j][k]
__device__ __forceinline__ void idct1(float* v) {
  float i0 = v[0], i1 = v[1], i2 = v[2], i3 = v[3];
  float i4 = v[4], i5 = v[5], i6 = v[6], i7 = v[7];
#pragma unroll
  for (int k = 0; k < 4; ++k) {
    float ev = i0 + Dm[2][k]*i2 + Dm[4][k]*i4 + Dm[6][k]*i6;
    float od = Dm[1][k]*i1 + Dm[3][k]*i3 + Dm[5][k]*i5 + Dm[7][k]*i7;
    v[k]     = ev + od;
    v[7 - k] = ev - od;
  }
}

__global__ void __launch_bounds__(256, 4)
jpeg_kernel(const float* __restrict__ in, float* __restrict__ out) {
  extern __shared__ float sm[];         // 3*4096 planes + 128 SA + 128 SB
  float* sQA = sm + 12288;              // 0.25*au*av / Q
  float* sQB = sm + 12416;              // 0.25*au*av * Q

  const int tid = threadIdx.x;
  const int gx0 = blockIdx.x * 64;
  const int gy0 = blockIdx.y * 64;
  const size_t plane = (size_t)Hh * Ww;
  const size_t img = (size_t)blockIdx.z * 3 * plane;
  const float* __restrict__ pr = in + img;
  const float* __restrict__ pg = in + img + plane;
  const float* __restrict__ pb = in + img + 2 * plane;

  // ---- quant table fill ----
  if (tid < 128) {
    int tab = tid >> 6, uv = tid & 63, u = uv >> 3, v = uv & 7;
    float a = 0.25f * (u ? 1.f : 0.70710678118654752f)
                    * (v ? 1.f : 0.70710678118654752f);
    float Q = tab ? QC[uv] : QY[uv];
    sQA[tid] = a / Q;
    sQB[tid] = a * Q;
  }

  // ------- Phase 1: gmem -> YCbCr -> row DCT -> smem -------
#pragma unroll
  for (int it = 0; it < 2; ++it) {
    int i = tid + it * 256;             // 8-pixel segment id (0..511)
    int row = i >> 3;
    int col = (i & 7) << 3;
    size_t g = (size_t)(gy0 + row) * Ww + (gx0 + col);

    float y[8], cb[8], cr[8];
#pragma unroll
    for (int h = 0; h < 2; ++h) {       // two float4s per channel
      float4 r4 = *(const float4*)(pr + g + h * 4);
      float4 g4 = *(const float4*)(pg + g + h * 4);
      float4 b4 = *(const float4*)(pb + g + h * 4);
      float R[4] = { r4.x, r4.y, r4.z, r4.w };
      float G[4] = { g4.x, g4.y, g4.z, g4.w };
      float B[4] = { b4.x, b4.y, b4.z, b4.w };
#pragma unroll
      for (int q = 0; q < 4; ++q) {
        int idx = h * 4 + q;
        // (x+1)/2*255 folded into the 3x3
        y[idx]  = fmaf(38.1225f, R[q], fmaf(74.8425f, G[q], fmaf(14.535f, B[q], 127.5f)));
        cb[idx] = fmaf(-21.51384f, R[q], fmaf(-42.23616f, G[q], fmaf(63.75f, B[q], 128.f)));
        cr[idx] = fmaf(63.75f, R[q], fmaf(-53.38272f, G[q], fmaf(-10.36728f, B[q], 128.f)));
      }
    }
    dct1(y); dct1(cb); dct1(cr);

    int s0 = row * 64 + swzc(col);
    int s1 = row * 64 + swzc(col + 4);
    *(float4*)&sm[s0]        = make_float4(y[0], y[1], y[2], y[3]);
    *(float4*)&sm[s1]        = make_float4(y[4], y[5], y[6], y[7]);
    *(float4*)&sm[4096 + s0] = make_float4(cb[0], cb[1], cb[2], cb[3]);
    *(float4*)&sm[4096 + s1] = make_float4(cb[4], cb[5], cb[6], cb[7]);
    *(float4*)&sm[8192 + s0] = make_float4(cr[0], cr[1], cr[2], cr[3]);
    *(float4*)&sm[8192 + s1] = make_float4(cr[4], cr[5], cr[6], cr[7]);
  }
  __syncthreads();

  // --- Phase 2: col DCT + quantize(diff-round) + col IDCT (2 cols/thread) ---
  {
    const int col = (tid & 31) * 2;     // even column; pair (col, col+1)
    const int br  = tid >> 5;           // block-row (0..7)
    const int v0  = col & 7;            // freq index of first column
    const int base0 = br * 512 + swzc(col);   // swzc(col+1) == swzc(col)+1
#pragma unroll
    for (int k = 0; k < 3; ++k) {       // channel
      int base = k * 4096 + base0;
      float va[8], vb[8];
#pragma unroll
      for (int r = 0; r < 8; ++r) {
        float2 t = *(const float2*)&sm[base + r * 64];
        va[r] = t.x; vb[r] = t.y;
      }
      dct1(va); dct1(vb);
      if (v0 == 0) va[0] -= 8192.f;     // DC offset == (p-128) pre-DCT
      const int koff = k ? 64 : 0;
      const float* qa0 = &sQA[koff + v0];
      const float* qb0 = &sQB[koff + v0];
#pragma unroll
      for (int u = 0; u < 8; ++u) {
        float sa = va[u] * qa0[u * 8];
        float ra = rintf(sa);
        float da = sa - ra;
        va[u] = fmaf(da * da, da, ra) * qb0[u * 8];
        float sb = vb[u] * qa0[u * 8 + 1];
        float rb = rintf(sb);
        float db = sb - rb;
        vb[u] = fmaf(db * db, db, rb) * qb0[u * 8 + 1];
      }
      idct1(va); idct1(vb);
#pragma unroll
      for (int r = 0; r < 8; ++r)
        *(float2*)&sm[base + r * 64] = make_float2(va[r], vb[r]);
    }
  }
  __syncthreads();

  // ------- Phase 3: smem -> row IDCT -> YCbCr->RGB -> gmem -------
  float* __restrict__ qr = out + img;
  float* __restrict__ qg = out + img + plane;
  float* __restrict__ qb2 = out + img + 2 * plane;
#pragma unroll
  for (int it = 0; it < 2; ++it) {
    int i = tid + it * 256;
    int row = i >> 3;
    int col = (i & 7) << 3;
    int s0 = row * 64 + swzc(col);
    int s1 = row * 64 + swzc(col + 4);

    float y[8], cb[8], cr[8];
    float4 t0, t1;
    t0 = *(const float4*)&sm[s0];        t1 = *(const float4*)&sm[s1];
    y[0]=t0.x; y[1]=t0.y; y[2]=t0.z; y[3]=t0.w; y[4]=t1.x; y[5]=t1.y; y[6]=t1.z; y[7]=t1.w;
    t0 = *(const float4*)&sm[4096 + s0]; t1 = *(const float4*)&sm[4096 + s1];
    cb[0]=t0.x; cb[1]=t0.y; cb[2]=t0.z; cb[3]=t0.w; cb[4]=t1.x; cb[5]=t1.y; cb[6]=t1.z; cb[7]=t1.w;
    t0 = *(const float4*)&sm[8192 + s0]; t1 = *(const float4*)&sm[8192 + s1];
    cr[0]=t0.x; cr[1]=t0.y; cr[2]=t0.z; cr[3]=t0.w; cr[4]=t1.x; cr[5]=t1.y; cr[6]=t1.z; cr[7]=t1.w;

    idct1(y); idct1(cb); idct1(cr);

    size_t g = (size_t)(gy0 + row) * Ww + (gx0 + col);
#pragma unroll
    for (int h = 0; h < 2; ++h) {
      float R[4], G[4], B[4];
#pragma unroll
      for (int q = 0; q < 4; ++q) {
        int idx = h * 4 + q;
        float y128 = y[idx] + 128.f;    // recon is centered; re-add 128 (DC trick)
        float r = fmaf(1.402f, cr[idx], y128);
        float gg = fmaf(-0.714136f, cr[idx], fmaf(-0.344136f, cb[idx], y128));
        float b = fmaf(1.772f, cb[idx], y128);
        const float inv255 = 1.0f / 255.0f;
        R[q] = fminf(fmaxf(r, 0.f), 255.f) * inv255;
        G[q] = fminf(fmaxf(gg, 0.f), 255.f) * inv255;
        B[q] = fminf(fmaxf(b, 0.f), 255.f) * inv255;
      }
      *(float4*)(qr + g + h * 4)  = make_float4(R[0], R[1], R[2], R[3]);
      *(float4*)(qg + g + h * 4)  = make_float4(G[0], G[1], G[2], G[3]);
      *(float4*)(qb2 + g + h * 4) = make_float4(B[0], B[1], B[2], B[3]);
    }
  }
}

} // namespace

extern "C" void kernel_launch(void* const* d_in, const int* in_sizes, int n_in,
                              void* d_out, int out_size) {
  (void)in_sizes; (void)n_in; (void)out_size;
  const float* in = (const float*)d_in[0];
  float* out = (float*)d_out;
  constexpr int SMEM = (3 * 4096 + 256) * 4;   // 50176 bytes
  static bool attr_set = false;
  if (!attr_set) {
    cudaFuncSetAttribute(jpeg_kernel, cudaFuncAttributeMaxDynamicSharedMemorySize, SMEM);
    attr_set = true;
  }
  dim3 grid(Ww / 64, Hh / 64, 16);
  jpeg_kernel<<<grid, 256, SMEM>>>(in, out);
}

// round 6
// speedup vs baseline: 1.1523x; 1.1523x over previous
#include <cuda_runtime.h>

// JPEG compress/decompress (DiffJPEG, factor=1.0) for [16,3,512,512] fp32 in [-1,1].
// One CTA = one 64x64 tile, 256 threads, 4 CTAs/SM.
// Lane-pair row transforms: lanes (2j,2j+1) share one 8-pixel row segment via
// shfl_xor(1) butterflies; each lane computes 4 of 8 frequencies (even lane:
// 0,2,4,6; odd lane: 1,3,5,7), stored permuted. Quant tables are pre-permuted.
// Phase 1: gmem (coalesced float4) -> YCbCr -> half row-DCT -> smem
// Phase 2: column DCT + diff-round quant + column IDCT (scalar, conflict-free)
// Phase 3: smem -> half row-IDCT -> YCbCr->RGB -> gmem (coalesced float4)
// DC trick: subtract 128*64 from the DC coefficient; re-add 128 at output.

namespace {

constexpr int Hh = 512;
constexpr int Ww = 512;

// Forward half-transform coefs: CF[p][m][k] = Dm[2m+p][k], k=0..3
__constant__ float CF[32] = {
  // p=0 (even lanes): rows Dm[0], Dm[2], Dm[4], Dm[6]
  1.f,          1.f,          1.f,          1.f,
  0.92387953f,  0.38268343f, -0.38268343f, -0.92387953f,
  0.70710678f, -0.70710678f, -0.70710678f,  0.70710678f,
  0.38268343f, -0.92387953f,  0.92387953f, -0.38268343f,
  // p=1 (odd lanes): rows Dm[1], Dm[3], Dm[5], Dm[7]
  0.98078528f,  0.83146961f,  0.55557023f,  0.19509032f,
  0.83146961f, -0.19509032f, -0.98078528f, -0.55557023f,
  0.55557023f, -0.98078528f,  0.19509032f,  0.83146961f,
  0.19509032f, -0.55557023f,  0.83146961f, -0.98078528f,
};
// Inverse half-transform coefs: CI[p][k][m] = Dm[2m+p][k]
__constant__ float CI[32] = {
  // p=0: ev_k = sum_m CI[k][m] * F_{2m}
  1.f,  0.92387953f,  0.70710678f,  0.38268343f,
  1.f,  0.38268343f, -0.70710678f, -0.92387953f,
  1.f, -0.38268343f, -0.70710678f,  0.92387953f,
  1.f, -0.92387953f,  0.70710678f, -0.38268343f,
  // p=1: od_k = sum_m CI[k][m] * F_{2m+1}  (odd-odd block is symmetric)
  0.98078528f,  0.83146961f,  0.55557023f,  0.19509032f,
  0.83146961f, -0.19509032f, -0.98078528f, -0.55557023f,
  0.55557023f, -0.98078528f,  0.19509032f,  0.83146961f,
  0.19509032f, -0.55557023f,  0.83146961f, -0.98078528f,
};

// Full 8-point DCT basis for the column pass: Dm[u][x] = cos((2x+1)u pi/16)
__device__ static constexpr float Dm[8][8] = {
  { 1.f,          1.f,          1.f,          1.f,          1.f,          1.f,          1.f,          1.f         },
  { 0.98078528f,  0.83146961f,  0.55557023f,  0.19509032f, -0.19509032f, -0.55557023f, -0.83146961f, -0.98078528f },
  { 0.92387953f,  0.38268343f, -0.38268343f, -0.92387953f, -0.92387953f, -0.38268343f,  0.38268343f,  0.92387953f },
  { 0.83146961f, -0.19509032f, -0.98078528f, -0.55557023f,  0.55557023f,  0.98078528f,  0.19509032f, -0.83146961f },
  { 0.70710678f, -0.70710678f, -0.70710678f,  0.70710678f,  0.70710678f, -0.70710678f, -0.70710678f,  0.70710678f },
  { 0.55557023f, -0.98078528f,  0.19509032f,  0.83146961f, -0.83146961f, -0.19509032f,  0.98078528f, -0.55557023f },
  { 0.38268343f, -0.92387953f,  0.92387953f, -0.38268343f, -0.38268343f,  0.92387953f, -0.92387953f,  0.38268343f },
  { 0.19509032f, -0.55557023f,  0.83146961f, -0.98078528f,  0.98078528f, -0.83146961f,  0.55557023f, -0.19509032f },
};

__device__ static const float QY[64] = {
  16, 11, 10, 16, 24, 40, 51, 61,
  12, 12, 14, 19, 26, 58, 60, 55,
  14, 13, 16, 24, 40, 57, 69, 56,
  14, 17, 22, 29, 51, 87, 80, 62,
  18, 22, 37, 56, 68, 109, 103, 77,
  24, 35, 55, 64, 81, 104, 113, 92,
  49, 64, 78, 87, 103, 121, 120, 101,
  72, 92, 95, 98, 112, 100, 103, 99
};
__device__ static const float QC[64] = {
  17, 18, 24, 47, 99, 99, 99, 99,
  18, 21, 26, 66, 99, 99, 99, 99,
  24, 26, 56, 99, 99, 99, 99, 99,
  47, 66, 99, 99, 99, 99, 99, 99,
  99, 99, 99, 99, 99, 99, 99, 99,
  99, 99, 99, 99, 99, 99, 99, 99,
  99, 99, 99, 99, 99, 99, 99, 99,
  99, 99, 99, 99, 99, 99, 99, 99
};

__device__ __forceinline__ int swzc(int c) { return c ^ ((c & 32) >> 3); }

// Column-pass 8-point DCT/IDCT (immediates, even/odd split)
__device__ __forceinline__ void dct1(float* v) {
  float e0 = v[0] + v[7], e1 = v[1] + v[6], e2 = v[2] + v[5], e3 = v[3] + v[4];
  float o0 = v[0] - v[7], o1 = v[1] - v[6], o2 = v[2] - v[5], o3 = v[3] - v[4];
  v[0] = (e0 + e3) + (e1 + e2);
  v[4] = Dm[4][0] * ((e0 + e3) - (e1 + e2));
  v[2] = Dm[2][0]*e0 + Dm[2][1]*e1 + Dm[2][2]*e2 + Dm[2][3]*e3;
  v[6] = Dm[6][0]*e0 + Dm[6][1]*e1 + Dm[6][2]*e2 + Dm[6][3]*e3;
  v[1] = Dm[1][0]*o0 + Dm[1][1]*o1 + Dm[1][2]*o2 + Dm[1][3]*o3;
  v[3] = Dm[3][0]*o0 + Dm[3][1]*o1 + Dm[3][2]*o2 + Dm[3][3]*o3;
  v[5] = Dm[5][0]*o0 + Dm[5][1]*o1 + Dm[5][2]*o2 + Dm[5][3]*o3;
  v[7] = Dm[7][0]*o0 + Dm[7][1]*o1 + Dm[7][2]*o2 + Dm[7][3]*o3;
}
__device__ __forceinline__ void idct1(float* v) {
  float i0 = v[0], i1 = v[1], i2 = v[2], i3 = v[3];
  float i4 = v[4], i5 = v[5], i6 = v[6], i7 = v[7];
#pragma unroll
  for (int k = 0; k < 4; ++k) {
    float ev = i0 + Dm[2][k]*i2 + Dm[4][k]*i4 + Dm[6][k]*i6;
    float od = Dm[1][k]*i1 + Dm[3][k]*i3 + Dm[5][k]*i5 + Dm[7][k]*i7;
    v[k]     = ev + od;
    v[7 - k] = ev - od;
  }
}

// Half row-DCT: lane pair (2j,2j+1). Even lane holds pixels 8j..8j+3 (natural),
// odd lane holds pixels 8j+7..8j+4 (pre-reversed). Produces 4 freqs per lane
// (even: 0,2,4,6; odd: 1,3,5,7).
__device__ __forceinline__ void half_dct(float v[4], const float cf[16], float sgn) {
  float t0 = __shfl_xor_sync(0xffffffffu, v[0], 1);
  float t1 = __shfl_xor_sync(0xffffffffu, v[1], 1);
  float t2 = __shfl_xor_sync(0xffffffffu, v[2], 1);
  float t3 = __shfl_xor_sync(0xffffffffu, v[3], 1);
  float x0 = fmaf(sgn, v[0], t0);   // even: e_k ; odd: o_k
  float x1 = fmaf(sgn, v[1], t1);
  float x2 = fmaf(sgn, v[2], t2);
  float x3 = fmaf(sgn, v[3], t3);
  v[0] = fmaf(cf[3],  x3, fmaf(cf[2],  x2, fmaf(cf[1],  x1, cf[0]  * x0)));
  v[1] = fmaf(cf[7],  x3, fmaf(cf[6],  x2, fmaf(cf[5],  x1, cf[4]  * x0)));
  v[2] = fmaf(cf[11], x3, fmaf(cf[10], x2, fmaf(cf[9],  x1, cf[8]  * x0)));
  v[3] = fmaf(cf[15], x3, fmaf(cf[14], x2, fmaf(cf[13], x1, cf[12] * x0)));
}

// Half row-IDCT: even lane input F0,F2,F4,F6; odd lane F1,F3,F5,F7.
// Output: even lane pixels 8j+k (natural); odd lane pixels 8j+7-k (reversed).
__device__ __forceinline__ void half_idct(float f[4], const float ci[16], float sgn) {
  float g0 = fmaf(ci[3],  f[3], fmaf(ci[2],  f[2], fmaf(ci[1],  f[1], ci[0]  * f[0])));
  float g1 = fmaf(ci[7],  f[3], fmaf(ci[6],  f[2], fmaf(ci[5],  f[1], ci[4]  * f[0])));
  float g2 = fmaf(ci[11], f[3], fmaf(ci[10], f[2], fmaf(ci[9],  f[1], ci[8]  * f[0])));
  float g3 = fmaf(ci[15], f[3], fmaf(ci[14], f[2], fmaf(ci[13], f[1], ci[12] * f[0])));
  float t0 = __shfl_xor_sync(0xffffffffu, g0, 1);
  float t1 = __shfl_xor_sync(0xffffffffu, g1, 1);
  float t2 = __shfl_xor_sync(0xffffffffu, g2, 1);
  float t3 = __shfl_xor_sync(0xffffffffu, g3, 1);
  f[0] = fmaf(sgn, g0, t0);   // even: ev+od ; odd: ev-od (reversed position)
  f[1] = fmaf(sgn, g1, t1);
  f[2] = fmaf(sgn, g2, t2);
  f[3] = fmaf(sgn, g3, t3);
}

__global__ void __launch_bounds__(256, 4)
jpeg_kernel(const float* __restrict__ in, float* __restrict__ out) {
  extern __shared__ float sm[];         // 3*4096 planes + 128 SA + 128 SB
  float* sQA = sm + 12288;              // permuted: 0.25*au*av / Q
  float* sQB = sm + 12416;              // permuted: 0.25*au*av * Q

  const int tid = threadIdx.x;
  const bool oddl = (tid & 1) != 0;
  const float sgn = oddl ? -1.f : 1.f;
  const int gx0 = blockIdx.x * 64;
  const int gy0 = blockIdx.y * 64;
  const size_t plane = (size_t)Hh * Ww;
  const size_t img = (size_t)blockIdx.z * 3 * plane;
  const float* __restrict__ pr = in + img;
  const float* __restrict__ pg = in + img + plane;
  const float* __restrict__ pb = in + img + 2 * plane;

  // ---- quant table fill (slot s holds freq perm[s] = {0,2,4,6,1,3,5,7}) ----
  if (tid < 128) {
    int tab = tid >> 6, uv = tid & 63, u = uv >> 3, s = uv & 7;
    int v = (s < 4) ? (s << 1) : ((s << 1) - 7);
    float a = 0.25f * (u ? 1.f : 0.70710678118654752f)
                    * (v ? 1.f : 0.70710678118654752f);
    float Q = tab ? QC[u * 8 + v] : QY[u * 8 + v];
    sQA[tid] = a / Q;
    sQB[tid] = a * Q;
  }

  // ------- Phase 1: gmem -> YCbCr -> half row-DCT -> smem -------
  {
    float cf[16];
    const float* cfp = CF + (oddl ? 16 : 0);
#pragma unroll
    for (int t = 0; t < 16; ++t) cf[t] = cfp[t];

#pragma unroll
    for (int it = 0; it < 4; ++it) {
      int i = tid + it * 256;
      int row = i >> 4;
      int c4 = (i & 15) << 2;
      size_t g = (size_t)(gy0 + row) * Ww + (gx0 + c4);
      float4 r4 = *(const float4*)(pr + g);
      float4 g4 = *(const float4*)(pg + g);
      float4 b4 = *(const float4*)(pb + g);

      // odd lanes reverse their 4 pixels (pixel order 8j+7..8j+4)
      float R[4], G[4], B[4];
      R[0] = oddl ? r4.w : r4.x;  R[1] = oddl ? r4.z : r4.y;
      R[2] = oddl ? r4.y : r4.z;  R[3] = oddl ? r4.x : r4.w;
      G[0] = oddl ? g4.w : g4.x;  G[1] = oddl ? g4.z : g4.y;
      G[2] = oddl ? g4.y : g4.z;  G[3] = oddl ? g4.x : g4.w;
      B[0] = oddl ? b4.w : b4.x;  B[1] = oddl ? b4.z : b4.y;
      B[2] = oddl ? b4.y : b4.z;  B[3] = oddl ? b4.x : b4.w;

      float y[4], cb[4], cr[4];
#pragma unroll
      for (int q = 0; q < 4; ++q) {
        // (x+1)/2*255 folded into the 3x3
        y[q]  = fmaf(38.1225f,  R[q], fmaf(74.8425f,  G[q], fmaf(14.535f,   B[q], 127.5f)));
        cb[q] = fmaf(-21.51384f, R[q], fmaf(-42.23616f, G[q], fmaf(63.75f,   B[q], 128.f)));
        cr[q] = fmaf(63.75f,    R[q], fmaf(-53.38272f, G[q], fmaf(-10.36728f, B[q], 128.f)));
      }
      half_dct(y, cf, sgn);
      half_dct(cb, cf, sgn);
      half_dct(cr, cf, sgn);

      int s = row * 64 + swzc(c4);
      *(float4*)&sm[s]        = make_float4(y[0], y[1], y[2], y[3]);
      *(float4*)&sm[4096 + s] = make_float4(cb[0], cb[1], cb[2], cb[3]);
      *(float4*)&sm[8192 + s] = make_float4(cr[0], cr[1], cr[2], cr[3]);
    }
  }
  __syncthreads();

  // --- Phase 2: col DCT + diff-round quant + col IDCT (scalar, conflict-free) ---
  {
    const int colb = tid & 63;
    const int slot = colb & 7;          // permuted freq slot
    const int brb = tid >> 6;           // 0..3
    const int sw = swzc(colb);
    float qa[8], qb[8];
#pragma unroll
    for (int k = 0; k < 3; ++k) {       // channel
      if (k < 2) {                      // k=2 (Cr) reuses C tables from k=1
        const int koff = k ? 64 : 0;
#pragma unroll
        for (int u = 0; u < 8; ++u) {
          qa[u] = sQA[koff + slot + u * 8];
          qb[u] = sQB[koff + slot + u * 8];
        }
      }
#pragma unroll
      for (int half = 0; half < 2; ++half) {
        int base = k * 4096 + (brb + half * 4) * 512 + sw;
        float vec[8];
#pragma unroll
        for (int r = 0; r < 8; ++r) vec[r] = sm[base + r * 64];
        dct1(vec);
        if (slot == 0) vec[0] -= 8192.f;   // DC offset == (p-128) pre-DCT
#pragma unroll
        for (int u = 0; u < 8; ++u) {
          float s = vec[u] * qa[u];
          float r = rintf(s);              // half-to-even == jnp.round
          float d = s - r;
          vec[u] = fmaf(d * d, d, r) * qb[u];
        }
        idct1(vec);
#pragma unroll
        for (int r = 0; r < 8; ++r) sm[base + r * 64] = vec[r];
      }
    }
  }
  __syncthreads();

  // ------- Phase 3: smem -> half row-IDCT -> YCbCr->RGB -> gmem -------
  {
    float ci[16];
    const float* cip = CI + (oddl ? 16 : 0);
#pragma unroll
    for (int t = 0; t < 16; ++t) ci[t] = cip[t];

    float* __restrict__ qr = out + img;
    float* __restrict__ qg = out + img + plane;
    float* __restrict__ qb2 = out + img + 2 * plane;

#pragma unroll
    for (int it = 0; it < 4; ++it) {
      int i = tid + it * 256;
      int row = i >> 4;
      int c4 = (i & 15) << 2;
      int s = row * 64 + swzc(c4);

      float4 y4  = *(const float4*)&sm[s];
      float4 cb4 = *(const float4*)&sm[4096 + s];
      float4 cr4 = *(const float4*)&sm[8192 + s];
      float y[4]  = { y4.x, y4.y, y4.z, y4.w };
      float cb[4] = { cb4.x, cb4.y, cb4.z, cb4.w };
      float cr[4] = { cr4.x, cr4.y, cr4.z, cr4.w };

      half_idct(y, ci, sgn);
      half_idct(cb, ci, sgn);
      half_idct(cr, ci, sgn);

      // odd lanes: results are in reversed pixel order -> un-reverse
      float yy[4], cbb[4], crr[4];
      yy[0]  = oddl ? y[3]  : y[0];   yy[1]  = oddl ? y[2]  : y[1];
      yy[2]  = oddl ? y[1]  : y[2];   yy[3]  = oddl ? y[0]  : y[3];
      cbb[0] = oddl ? cb[3] : cb[0];  cbb[1] = oddl ? cb[2] : cb[1];
      cbb[2] = oddl ? cb[1] : cb[2];  cbb[3] = oddl ? cb[0] : cb[3];
      crr[0] = oddl ? cr[3] : cr[0];  crr[1] = oddl ? cr[2] : cr[1];
      crr[2] = oddl ? cr[1] : cr[2];  crr[3] = oddl ? cr[0] : cr[3];

      float R[4], G[4], B[4];
#pragma unroll
      for (int q = 0; q < 4; ++q) {
        float y128 = yy[q] + 128.f;   // recon is centered (DC trick)
        float r = fmaf(1.402f, crr[q], y128);
        float gg = fmaf(-0.714136f, crr[q], fmaf(-0.344136f, cbb[q], y128));
        float b = fmaf(1.772f, cbb[q], y128);
        const float inv255 = 1.0f / 255.0f;
        R[q] = fminf(fmaxf(r, 0.f), 255.f) * inv255;
        G[q] = fminf(fmaxf(gg, 0.f), 255.f) * inv255;
        B[q] = fminf(fmaxf(b, 0.f), 255.f) * inv255;
      }
      size_t g = (size_t)(gy0 + row) * Ww + (gx0 + c4);
      *(float4*)(qr + g)  = make_float4(R[0], R[1], R[2], R[3]);
      *(float4*)(qg + g)  = make_float4(G[0], G[1], G[2], G[3]);
      *(float4*)(qb2 + g) = make_float4(B[0], B[1], B[2], B[3]);
    }
  }
}

} // namespace

extern "C" void kernel_launch(void* const* d_in, const int* in_sizes, int n_in,
                              void* d_out, int out_size) {
  (void)in_sizes; (void)n_in; (void)out_size;
  const float* in = (const float*)d_in[0];
  float* out = (float*)d_out;
  constexpr int SMEM = (3 * 4096 + 256) * 4;   // 50176 bytes
  static bool attr_set = false;
  if (!attr_set) {
    cudaFuncSetAttribute(jpeg_kernel, cudaFuncAttributeMaxDynamicSharedMemorySize, SMEM);
    attr_set = true;
  }
  dim3 grid(Ww / 64, Hh / 64, 16);
  jpeg_kernel<<<grid, 256, SMEM>>>(in, out);
}